// round 1
// baseline (speedup 1.0000x reference)
#include <cuda_runtime.h>
#include <math.h>

#ifndef M_PI
#define M_PI 3.14159265358979323846
#endif

#define ANGN 9
#define NUV 81
#define CH 3
#define HH 128
#define NF 16
#define NBLK 2
#define HW (HH*HH)            // 16384
#define S_UVHW (NUV*HW)       // 1327104

// ---------------- device global scratch ----------------
__device__ float g_Ds[HH*HH];
__device__ float g_DsT[HH*HH];
__device__ float g_Da[81];
__device__ float g_DaT[81];

__device__ float g_b1[CH*S_UVHW];
__device__ float g_b2[CH*S_UVHW];
__device__ float g_y0[NF*S_UVHW];
__device__ float g_y1[NF*S_UVHW];
__device__ float g_y2[NF*S_UVHW];

// packed weights: branch order 0=dc,1=lo,2=mi,3=hi
__device__ float g_wi[4*NF*CH*27];        // init conv weights
__device__ float g_bi[4*NF];
__device__ float g_wb[4*NBLK*NF*NF*27];   // resblock conv weights
__device__ float g_bb[4*NBLK*NF];
__device__ float g_al[4*NBLK];            // prelu alphas

// ---------------- DCT matrix init ----------------
__global__ void init_mats_kernel() {
    int tid = blockIdx.x*blockDim.x + threadIdx.x;
    int stride = gridDim.x*blockDim.x;
    for (int idx = tid; idx < HH*HH; idx += stride) {
        int k = idx / HH, i = idx % HH;
        double v = cos(M_PI*(i+0.5)*k/(double)HH) * sqrt(2.0/HH);
        if (k==0) v *= 0.70710678118654752440;
        float f = (float)v;
        g_Ds[k*HH+i] = f;
        g_DsT[i*HH+k] = f;
    }
    for (int idx = tid; idx < 81; idx += stride) {
        int k = idx/9, i = idx%9;
        double v = cos(M_PI*(i+0.5)*k/9.0)*sqrt(2.0/9.0);
        if (k==0) v *= 0.70710678118654752440;
        g_Da[k*9+i] = (float)v;
        g_DaT[i*9+k] = (float)v;
    }
}

// ---------------- weight packing ----------------
struct PackPtrs {
    const float* wi[4];
    const float* bi[4];
    const float* al[4];
    const float* wb[4];
    const float* bb[4];
};

__global__ void pack_kernel(PackPtrs pp) {
    int g = blockIdx.x*blockDim.x + threadIdx.x;
    int stride = gridDim.x*blockDim.x;
    for (int i = g; i < 4*NF*CH*27; i += stride) g_wi[i] = pp.wi[i/(NF*CH*27)][i%(NF*CH*27)];
    for (int i = g; i < 4*NF; i += stride)       g_bi[i] = pp.bi[i/NF][i%NF];
    for (int i = g; i < 4*NBLK; i += stride)     g_al[i] = pp.al[i/NBLK][i%NBLK];
    for (int i = g; i < 4*NBLK*NF*NF*27; i += stride) g_wb[i] = pp.wb[i/(NBLK*NF*NF*27)][i%(NBLK*NF*NF*27)];
    for (int i = g; i < 4*NBLK*NF; i += stride)  g_bb[i] = pp.bb[i/(NBLK*NF)][i%(NBLK*NF)];
}

// ---------------- spatial DCT: Y = M X M^T per 128x128 image ----------------
// mode 0: M = Ds, in = x (uv,c,h,w layout), out = g_b1 (c,uv,h,w)
// mode 1: M = DsT, in = g_b2 (c,uv,h,w), out = dout (uv,c,h,w) + x
#define DPAD 129
#define DCT_SMEM (3*HH*DPAD*4)

__global__ void dct_spatial_kernel(const float* __restrict__ x, float* __restrict__ dout, int mode) {
    extern __shared__ float sm[];
    float* Ms = sm;
    float* Xs = sm + HH*DPAD;
    float* Ts = sm + 2*HH*DPAD;
    int bid = blockIdx.x;           // 0..242
    int uv = bid / CH, c = bid % CH;
    int tid = threadIdx.x;

    const float* Msrc = mode ? g_DsT : g_Ds;
    const float* src  = mode ? (g_b2 + (c*NUV+uv)*HW) : (x + (uv*CH+c)*HW);

    for (int l = tid; l < HH*HH; l += 256) {
        int r = l >> 7, cc = l & 127;
        Ms[r*DPAD + cc] = Msrc[l];
        Xs[r*DPAD + cc] = src[l];
    }
    __syncthreads();

    int tx = tid & 15, ty = tid >> 4;
    float acc[8][8];
    #pragma unroll
    for (int i=0;i<8;i++)
        #pragma unroll
        for (int j=0;j<8;j++) acc[i][j] = 0.f;

    // stage 1: T = M * X
    for (int kk = 0; kk < HH; kk++) {
        float a[8], b[8];
        #pragma unroll
        for (int i=0;i<8;i++) a[i] = Ms[(ty+16*i)*DPAD + kk];
        #pragma unroll
        for (int j=0;j<8;j++) b[j] = Xs[kk*DPAD + tx + 16*j];
        #pragma unroll
        for (int i=0;i<8;i++)
            #pragma unroll
            for (int j=0;j<8;j++) acc[i][j] += a[i]*b[j];
    }
    #pragma unroll
    for (int i=0;i<8;i++)
        #pragma unroll
        for (int j=0;j<8;j++) Ts[(ty+16*i)*DPAD + tx+16*j] = acc[i][j];
    __syncthreads();

    #pragma unroll
    for (int i=0;i<8;i++)
        #pragma unroll
        for (int j=0;j<8;j++) acc[i][j] = 0.f;

    // stage 2: Y = T * M^T
    for (int kk = 0; kk < HH; kk++) {
        float a[8], b[8];
        #pragma unroll
        for (int i=0;i<8;i++) a[i] = Ts[(ty+16*i)*DPAD + kk];
        #pragma unroll
        for (int j=0;j<8;j++) b[j] = Ms[(tx+16*j)*DPAD + kk];
        #pragma unroll
        for (int i=0;i<8;i++)
            #pragma unroll
            for (int j=0;j<8;j++) acc[i][j] += a[i]*b[j];
    }

    if (mode == 0) {
        float* dst = g_b1 + (c*NUV+uv)*HW;
        #pragma unroll
        for (int i=0;i<8;i++)
            #pragma unroll
            for (int j=0;j<8;j++)
                dst[(ty+16*i)*HH + tx+16*j] = acc[i][j];
    } else {
        const float* xa = x + (uv*CH+c)*HW;
        float* dst = dout + (uv*CH+c)*HW;
        #pragma unroll
        for (int i=0;i<8;i++)
            #pragma unroll
            for (int j=0;j<8;j++) {
                int off = (ty+16*i)*HH + tx+16*j;
                dst[off] = acc[i][j] + xa[off];
            }
    }
}

// ---------------- angular DCT: per (c,h,w), O = M A M^T over 9x9 ----------------
// always in = g_b1, out = g_b2; mode0: M=Da, mode1: M=DaT
__global__ void dct_ang_kernel(int mode) {
    __shared__ float M[81];
    int tid = threadIdx.x;
    if (tid < 81) M[tid] = mode ? g_DaT[tid] : g_Da[tid];
    __syncthreads();
    int g = blockIdx.x*blockDim.x + tid;     // 0..49151
    if (g >= CH*HW) return;
    int c = g / HW, p = g % HW;

    const float* in = g_b1 + c*S_UVHW + p;
    float T[81];
    #pragma unroll
    for (int i=0;i<81;i++) T[i] = 0.f;

    #pragma unroll
    for (int u=0;u<9;u++) {
        #pragma unroll
        for (int v=0;v<9;v++) {
            float xv = in[(u*9+v)*HW];
            #pragma unroll
            for (int U=0;U<9;U++) T[U*9+v] += M[U*9+u]*xv;
        }
    }
    float* outp = g_b2 + c*S_UVHW + p;
    #pragma unroll
    for (int U=0;U<9;U++) {
        #pragma unroll
        for (int V=0;V<9;V++) {
            float o = 0.f;
            #pragma unroll
            for (int v=0;v<9;v++) o += T[U*9+v]*M[V*9+v];
            outp[(U*9+V)*HW] = o;
        }
    }
}

// ---------------- 3x3x3 conv over (uv-diagonal, h, w) ----------------
// tile: 16 rows x 64 cols, 256 threads, each thread 4 px, 16 out channels.
// smem: weights (CIN*NF*27) + bias (NF) + double-buffered 3-plane tiles (2*3*18*66)
#define TPL (18*66)          // 1188
#define TPL3 (3*TPL)         // 3564
#define CONVB_SMEM ((NF*NF*27 + NF + 2*TPL3)*4)
#define CONVI_SMEM ((CH*NF*27 + NF + 2*TPL3)*4)

template<int CIN, bool PRELU, bool RES>
__device__ __forceinline__ void conv3d_body(
    const float* __restrict__ in, const float* __restrict__ res,
    float* __restrict__ out,
    const float* __restrict__ Wsel, const float* __restrict__ Bsel, float alpha)
{
    extern __shared__ float sm[];
    float* sw = sm;
    float* sb = sw + CIN*NF*27;
    float* st = sb + NF;

    const int tid = threadIdx.x;
    const int tx = tid & 15, ty = tid >> 4;
    const int uv = blockIdx.z;
    const int u = uv/9, v = uv - 9*u;
    const int h0 = blockIdx.y*16, w0 = blockIdx.x*64;
    const int nb0 = (u > 0 && v < 8) ? uv-8 : -1;   // (u-1,v+1)
    const int nb2 = (u < 8 && v > 0) ? uv+8 : -1;   // (u+1,v-1)

    for (int l = tid; l < CIN*NF*27; l += 256) sw[l] = Wsel[l];
    if (tid < NF) sb[tid] = Bsel[tid];

    auto ldval = [&](int ic, int l) -> float {
        int d = l / TPL;
        int rem = l - d*TPL;
        int r = rem / 66;
        int cc = rem - r*66;
        int gh = h0 - 1 + r, gw = w0 - 1 + cc;
        int uvd = (d==0) ? nb0 : ((d==1) ? uv : nb2);
        float val = 0.f;
        if (uvd >= 0 && (unsigned)gh < (unsigned)HH && (unsigned)gw < (unsigned)HH) {
            val = in[((ic*NUV+uvd) << 14) + (gh << 7) + gw];
            if (PRELU) val = (val >= 0.f) ? val : alpha*val;
        }
        return val;
    };

    // load ic=0 into buffer 0
    #pragma unroll
    for (int j = 0; j < 14; j++) {
        int l = tid + j*256;
        if (l < TPL3) st[l] = ldval(0, l);
    }
    __syncthreads();

    float acc[NF][4];
    #pragma unroll
    for (int o=0;o<NF;o++)
        #pragma unroll
        for (int p=0;p<4;p++) acc[o][p] = 0.f;

    #pragma unroll 1
    for (int ic = 0; ic < CIN; ic++) {
        const int cur = ic & 1;
        float pre[14];
        if (ic + 1 < CIN) {
            #pragma unroll
            for (int j = 0; j < 14; j++) {
                int l = tid + j*256;
                pre[j] = (l < TPL3) ? ldval(ic+1, l) : 0.f;
            }
        }
        const float* base = st + cur*TPL3;
        const float* wic = sw + ic*27;
        #pragma unroll 1
        for (int d = 0; d < 3; d++) {
            #pragma unroll 1
            for (int dh = 0; dh < 3; dh++) {
                const float* row = base + d*TPL + (ty+dh)*66 + tx*4;
                float i0=row[0], i1=row[1], i2=row[2], i3=row[3], i4=row[4], i5=row[5];
                const float* wt = wic + d*9 + dh*3;
                #pragma unroll
                for (int dw = 0; dw < 3; dw++) {
                    float v0 = (dw==0)?i0:((dw==1)?i1:i2);
                    float v1 = (dw==0)?i1:((dw==1)?i2:i3);
                    float v2 = (dw==0)?i2:((dw==1)?i3:i4);
                    float v3 = (dw==0)?i3:((dw==1)?i4:i5);
                    #pragma unroll
                    for (int o = 0; o < NF; o++) {
                        float wv = wt[o*(CIN*27) + dw];
                        acc[o][0] += v0*wv;
                        acc[o][1] += v1*wv;
                        acc[o][2] += v2*wv;
                        acc[o][3] += v3*wv;
                    }
                }
            }
        }
        if (ic + 1 < CIN) {
            float* nbuf = st + (cur^1)*TPL3;
            #pragma unroll
            for (int j = 0; j < 14; j++) {
                int l = tid + j*256;
                if (l < TPL3) nbuf[l] = pre[j];
            }
            __syncthreads();
        }
    }

    const int gh = h0 + ty;
    #pragma unroll
    for (int o = 0; o < NF; o++) {
        float bias = sb[o];
        int obase = ((o*NUV+uv) << 14) + (gh << 7) + w0 + tx*4;
        #pragma unroll
        for (int p = 0; p < 4; p++) {
            float vv = acc[o][p] + bias;
            if (RES) vv += res[obase + p];
            out[obase + p] = vv;
        }
    }
}

__device__ __forceinline__ int branch_idx(int uv) {
    int u = uv/9, s = u + (uv - 9*u);
    return (s==0) ? 0 : (s<=2 ? 1 : (s<=8 ? 2 : 3));
}

__global__ void __launch_bounds__(256,2) conv_init_kernel() {
    int widx = branch_idx(blockIdx.z);
    conv3d_body<CH,false,false>(g_b2, nullptr, g_y0,
        g_wi + widx*(NF*CH*27), g_bi + widx*NF, 0.f);
}

__global__ void __launch_bounds__(256,2) conv_block_kernel(int k) {
    int widx = branch_idx(blockIdx.z);
    const float* in = (k==0) ? g_y0 : g_y1;
    float* out = (k==0) ? g_y1 : g_y2;
    int sel = widx*NBLK + k;
    conv3d_body<NF,true,true>(in, in, out,
        g_wb + sel*(NF*NF*27), g_bb + sel*NF, g_al[sel]);
}

// ---------------- 1x1 mix: out[c] = sum_n wl[c,n]*(y0[n]+y2[n]) ----------------
__global__ void mix_kernel(const float* __restrict__ wl) {
    __shared__ float w[CH*NF];
    if (threadIdx.x < CH*NF) w[threadIdx.x] = wl[threadIdx.x];
    __syncthreads();
    int t = blockIdx.x*blockDim.x + threadIdx.x;
    const int S4 = S_UVHW/4;
    if (t >= S4) return;
    float4 a0 = make_float4(0,0,0,0), a1 = a0, a2 = a0;
    #pragma unroll
    for (int n = 0; n < NF; n++) {
        float4 y = ((const float4*)g_y0)[n*S4 + t];
        float4 z = ((const float4*)g_y2)[n*S4 + t];
        float sx = y.x+z.x, sy = y.y+z.y, sz = y.z+z.z, swv = y.w+z.w;
        float w0 = w[0*NF+n], w1 = w[1*NF+n], w2 = w[2*NF+n];
        a0.x += w0*sx; a0.y += w0*sy; a0.z += w0*sz; a0.w += w0*swv;
        a1.x += w1*sx; a1.y += w1*sy; a1.z += w1*sz; a1.w += w1*swv;
        a2.x += w2*sx; a2.y += w2*sy; a2.z += w2*sz; a2.w += w2*swv;
    }
    ((float4*)g_b1)[0*S4 + t] = a0;
    ((float4*)g_b1)[1*S4 + t] = a1;
    ((float4*)g_b1)[2*S4 + t] = a2;
}

// ---------------- launch ----------------
extern "C" void kernel_launch(void* const* d_in, const int* in_sizes, int n_in,
                              void* d_out, int out_size) {
    const float* x = (const float*)d_in[0];
    PackPtrs pp;
    for (int t = 0; t < 4; t++) {
        int base = 1 + t*5;
        pp.wi[t] = (const float*)d_in[base+0];
        pp.bi[t] = (const float*)d_in[base+1];
        pp.al[t] = (const float*)d_in[base+2];
        pp.wb[t] = (const float*)d_in[base+3];
        pp.bb[t] = (const float*)d_in[base+4];
    }
    const float* wl = (const float*)d_in[21];
    float* out = (float*)d_out;

    cudaFuncSetAttribute(dct_spatial_kernel, cudaFuncAttributeMaxDynamicSharedMemorySize, DCT_SMEM);
    cudaFuncSetAttribute(conv_block_kernel, cudaFuncAttributeMaxDynamicSharedMemorySize, CONVB_SMEM);
    cudaFuncSetAttribute(conv_init_kernel, cudaFuncAttributeMaxDynamicSharedMemorySize, CONVI_SMEM);

    init_mats_kernel<<<64, 256>>>();
    pack_kernel<<<64, 256>>>(pp);

    dct_spatial_kernel<<<243, 256, DCT_SMEM>>>(x, out, 0);   // x -> g_b1
    dct_ang_kernel<<<192, 256>>>(0);                          // g_b1 -> g_b2

    dim3 cg(2, 8, NUV);
    conv_init_kernel<<<cg, 256, CONVI_SMEM>>>();              // g_b2 -> g_y0
    conv_block_kernel<<<cg, 256, CONVB_SMEM>>>(0);            // g_y0 -> g_y1
    conv_block_kernel<<<cg, 256, CONVB_SMEM>>>(1);            // g_y1 -> g_y2

    mix_kernel<<<(S_UVHW/4 + 255)/256, 256>>>(wl);            // y0+y2 -> g_b1

    dct_ang_kernel<<<192, 256>>>(1);                          // g_b1 -> g_b2
    dct_spatial_kernel<<<243, 256, DCT_SMEM>>>(x, out, 1);    // g_b2 -> out (+x)
}